// round 7
// baseline (speedup 1.0000x reference)
#include <cuda_runtime.h>
#include <cstdint>

// Problem dims (fixed by the dataset)
#define T_   1024
#define B_   32
#define DIN_ 256
#define H_   256
#define AA_  21
#define M_   (T_*B_)   // 32768

// ---------------------------------------------------------------------------
// Scratch (device globals — no cudaMalloc allowed)
// ---------------------------------------------------------------------------
__device__ float g_U  [2u*32768u*1024u];  // per-dir U tensor [n][m][h*4+k], reused L0/L1 (268MB)
__device__ float g_h0 [32768u*512u];      // layer0 output  [m][dir*H + h]
__device__ float g_h1 [32768u*512u];      // layer1 output
__device__ float g_y  [32768u*256u];      // fc1 output
__device__ float g_w0p[2*256*1024];       // packed w_l0: [n][d][h*4+k]
__device__ float g_w1p[2*512*1024];       // packed w_l1
__device__ float g_fcp[512*256];          // packed fc1_w: [k][j]

// ---------------------------------------------------------------------------
// Weight packing (cheap, re-run every launch for determinism)
// ---------------------------------------------------------------------------
#define PACK_S0 (2*256*1024)
#define PACK_S1 (2*512*1024)
#define PACK_S2 (512*256)
#define PACK_TOTAL (PACK_S0 + PACK_S1 + PACK_S2)

__global__ void pack_kernel(const float* __restrict__ w0,
                            const float* __restrict__ w1,
                            const float* __restrict__ fcw,
                            float* __restrict__ w0p,
                            float* __restrict__ w1p,
                            float* __restrict__ fcp)
{
    int i = blockIdx.x * blockDim.x + threadIdx.x;
    if (i < PACK_S0) {
        int c = i & 1023, d = (i >> 10) & 255, n = i >> 18;
        int k = c & 3, h = c >> 2;
        w0p[i] = w0[((d*2 + n)*4 + k)*H_ + h];
        return;
    }
    int j = i - PACK_S0;
    if (j < PACK_S1) {
        int c = j & 1023, d = (j >> 10) & 511, n = j >> 19;
        int k = c & 3, h = c >> 2;
        w1p[j] = w1[((d*2 + n)*4 + k)*H_ + h];
        return;
    }
    int l = j - PACK_S1;
    if (l < PACK_S2) {
        int jj = l & 255, kk = l >> 8;
        fcp[l] = fcw[jj*512 + kk];
    }
}

// ---------------------------------------------------------------------------
// FP32 GEMM with packed fma.rn.f32x2 (Blackwell FFMA2, 2x FFMA throughput).
// C[m][c] = sum_k A[m][k] * B[k][c]  (+ optional bias[c])
// A row access: xmode=1 -> A is x (B,T,DIN) with m = t*B + b; else contiguous ld=K.
// Block tile 128x128, BK=16, 256 threads, 8x8 micro-tile / thread.
// A is stored DUPLICATED into SMEM as float2(a,a) so the inner loop is pure
// LDS.64 + FFMA2 (no mov.b64 packing on the critical path).
// ---------------------------------------------------------------------------
#define BM 128
#define BN 128
#define BK 16

__global__ void __launch_bounds__(256)
gemm_f32x2(const float* __restrict__ A, const float* __restrict__ Bm,
           float* __restrict__ C, const float* __restrict__ bias,
           int K, int N, int ldc, int xmode)
{
    __shared__ __align__(16) float2 As2[BK][BM];  // 16KB (duplicated pairs)
    __shared__ __align__(16) float  Bs [BK][BN];  // 8KB

    const int tid = threadIdx.x;
    const int m0  = blockIdx.y * BM;
    const int n0  = blockIdx.x * BN;
    const int rg  = tid >> 4;   // 0..15 : row group (8 rows each)
    const int cg  = tid & 15;   // 0..15 : col group (8 cols each)

    unsigned long long acc[8][4];
#pragma unroll
    for (int i = 0; i < 8; i++)
#pragma unroll
        for (int p = 0; p < 4; p++) acc[i][p] = 0ull;

    for (int kt = 0; kt < K; kt += BK) {
        // --- load A tile (128 x 16), duplicate into (a,a) pairs, layout [k][m]
#pragma unroll
        for (int q = 0; q < 2; q++) {
            int f  = (tid << 1) + q;      // 0..511 float4 slots
            int ml = f >> 2;              // 0..127
            int k4 = (f & 3) << 2;        // 0,4,8,12
            int m  = m0 + ml;
            const float* ap;
            if (xmode) {
                int t = m >> 5, b = m & 31;             // m = t*B + b, B=32
                ap = A + ((size_t)b * T_ + t) * DIN_ + kt + k4;
            } else {
                ap = A + (size_t)m * K + kt + k4;
            }
            float4 v = *(const float4*)ap;
            As2[k4 + 0][ml] = make_float2(v.x, v.x);
            As2[k4 + 1][ml] = make_float2(v.y, v.y);
            As2[k4 + 2][ml] = make_float2(v.z, v.z);
            As2[k4 + 3][ml] = make_float2(v.w, v.w);
        }
        // --- load B tile (16 x 128)
#pragma unroll
        for (int q = 0; q < 2; q++) {
            int f  = (tid << 1) + q;
            int kl = f >> 5;              // 0..15
            int n4 = (f & 31) << 2;       // 0..124
            *(float4*)&Bs[kl][n4] =
                *(const float4*)(Bm + (size_t)(kt + kl) * N + n0 + n4);
        }
        __syncthreads();

#pragma unroll
        for (int kk = 0; kk < BK; kk++) {
            unsigned long long a[8], bq[4];
#pragma unroll
            for (int i = 0; i < 8; i++)
                a[i] = *(const unsigned long long*)&As2[kk][rg * 8 + i];
            const unsigned long long* bp =
                (const unsigned long long*)&Bs[kk][cg * 8];
#pragma unroll
            for (int p = 0; p < 4; p++) bq[p] = bp[p];
#pragma unroll
            for (int i = 0; i < 8; i++)
#pragma unroll
                for (int p = 0; p < 4; p++)
                    asm("fma.rn.f32x2 %0, %1, %2, %0;"
                        : "+l"(acc[i][p]) : "l"(a[i]), "l"(bq[p]));
        }
        __syncthreads();
    }

    // --- epilogue
#pragma unroll
    for (int i = 0; i < 8; i++) {
        int m = m0 + rg * 8 + i;
        float o[8];
#pragma unroll
        for (int p = 0; p < 4; p++) {
            o[2*p]   = __uint_as_float((unsigned)(acc[i][p] & 0xffffffffull));
            o[2*p+1] = __uint_as_float((unsigned)(acc[i][p] >> 32));
        }
        if (bias) {
#pragma unroll
            for (int j = 0; j < 8; j++) o[j] += bias[n0 + cg * 8 + j];
        }
        float4* cp = (float4*)(C + (size_t)m * ldc + n0 + cg * 8);
        cp[0] = make_float4(o[0], o[1], o[2], o[3]);
        cp[1] = make_float4(o[4], o[5], o[6], o[7]);
    }
}

// ---------------------------------------------------------------------------
// SRU recurrence: one thread per (dir, b, h) lane, 1024 sequential steps.
//   f = sigma(u1 + vf*c + bf); c' = f*c + (1-f)*u0
//   r = sigma(u2 + vr*c + br); h = r*c' + (1-r)*u3      (r uses OLD c)
// U layout per dir: [m = t*B+b][h*4 + k] -> float4 per (m,h).
// Output: Hout[m][dir*H + h].
// ---------------------------------------------------------------------------
__device__ __forceinline__ float sigm_(float x)
{
    return __fdividef(1.0f, 1.0f + __expf(-x));
}

__global__ void __launch_bounds__(256)
sru_scan(const float* __restrict__ U, const float* __restrict__ wc,
         const float* __restrict__ bb, float* __restrict__ Hout)
{
    int g   = blockIdx.x * blockDim.x + threadIdx.x;  // 0..16383
    int dir = g >> 13;
    int e   = g & 8191;
    int h   = e & 255;
    int b   = e >> 8;

    const float vf = wc[(dir*2 + 0)*H_ + h];
    const float vr = wc[(dir*2 + 1)*H_ + h];
    const float bf = bb[(dir*2 + 0)*H_ + h];
    const float br = bb[(dir*2 + 1)*H_ + h];

    const float4* Ud = (const float4*)(U + (size_t)dir * M_ * 1024u);
    float c = 0.0f;

    if (dir == 0) {
        for (int t = 0; t < T_; t++) {
            float4 u = Ud[(size_t)(t * B_ + b) * 256 + h];
            float f = sigm_(u.y + __fmaf_rn(vf, c, bf));
            float r = sigm_(u.z + __fmaf_rn(vr, c, br));
            c = __fmaf_rn(f, c - u.x, u.x);
            float hv = __fmaf_rn(r, c - u.w, u.w);
            Hout[(size_t)(t * B_ + b) * 512 + h] = hv;
        }
    } else {
        for (int t = T_ - 1; t >= 0; t--) {
            float4 u = Ud[(size_t)(t * B_ + b) * 256 + h];
            float f = sigm_(u.y + __fmaf_rn(vf, c, bf));
            float r = sigm_(u.z + __fmaf_rn(vr, c, br));
            c = __fmaf_rn(f, c - u.x, u.x);
            float hv = __fmaf_rn(r, c - u.w, u.w);
            Hout[(size_t)(t * B_ + b) * 512 + H_ + h] = hv;
        }
    }
}

// ---------------------------------------------------------------------------
// Head: logits = y @ lp_w^T + lp_b (K=256, N=21), then log_softmax over 21.
// One warp per row m. lp_w cached in SMEM. Output (B,T,AA): m = t*B + b.
// ---------------------------------------------------------------------------
__global__ void __launch_bounds__(256)
head_kernel(const float* __restrict__ Y, const float* __restrict__ lpw,
            const float* __restrict__ lpb, float* __restrict__ out)
{
    __shared__ float sw[AA_ * 256];
    for (int i = threadIdx.x; i < AA_ * 256; i += blockDim.x) sw[i] = lpw[i];
    __syncthreads();

    int warp = (blockIdx.x * blockDim.x + threadIdx.x) >> 5;
    int lane = threadIdx.x & 31;
    if (warp >= M_) return;

    const float* y = Y + (size_t)warp * 256;
    float yv[8];
#pragma unroll
    for (int i = 0; i < 8; i++) yv[i] = y[lane + 32 * i];

    float logit = 0.0f;
#pragma unroll
    for (int a = 0; a < AA_; a++) {
        float s = 0.0f;
#pragma unroll
        for (int i = 0; i < 8; i++) s += yv[i] * sw[a * 256 + lane + 32 * i];
#pragma unroll
        for (int o = 16; o; o >>= 1) s += __shfl_xor_sync(0xffffffffu, s, o);
        if (lane == a) logit = s;
    }

    float v = (lane < AA_) ? (logit + lpb[lane]) : -3.402823466e+38f;
    float mx = v;
#pragma unroll
    for (int o = 16; o; o >>= 1)
        mx = fmaxf(mx, __shfl_xor_sync(0xffffffffu, mx, o));
    float ev = (lane < AA_) ? __expf(v - mx) : 0.0f;
    float se = ev;
#pragma unroll
    for (int o = 16; o; o >>= 1) se += __shfl_xor_sync(0xffffffffu, se, o);
    float ls = __logf(se);

    if (lane < AA_) {
        int m = warp, t = m >> 5, b = m & 31;
        out[(size_t)b * T_ * AA_ + t * AA_ + lane] = v - mx - ls;
    }
}

// ---------------------------------------------------------------------------
// Launch: pack -> GEMM U0 (x2 dirs) -> scan0 -> GEMM U1 (x2) -> scan1
//         -> FC1 GEMM (+bias) -> head. All on default stream (capturable).
// ---------------------------------------------------------------------------
extern "C" void kernel_launch(void* const* d_in, const int* in_sizes, int n_in,
                              void* d_out, int out_size)
{
    const float* x   = (const float*)d_in[0];
    // d_in[1] = hidden (unused, as in reference)
    const float* w0  = (const float*)d_in[2];
    const float* wc0 = (const float*)d_in[3];
    const float* bb0 = (const float*)d_in[4];
    const float* w1  = (const float*)d_in[5];
    const float* wc1 = (const float*)d_in[6];
    const float* bb1 = (const float*)d_in[7];
    const float* fcw = (const float*)d_in[8];
    const float* fcb = (const float*)d_in[9];
    const float* lpw = (const float*)d_in[10];
    const float* lpb = (const float*)d_in[11];
    float* out = (float*)d_out;

    float *pU, *pH0, *pH1, *pY, *pW0, *pW1, *pFC;
    cudaGetSymbolAddress((void**)&pU,  g_U);
    cudaGetSymbolAddress((void**)&pH0, g_h0);
    cudaGetSymbolAddress((void**)&pH1, g_h1);
    cudaGetSymbolAddress((void**)&pY,  g_y);
    cudaGetSymbolAddress((void**)&pW0, g_w0p);
    cudaGetSymbolAddress((void**)&pW1, g_w1p);
    cudaGetSymbolAddress((void**)&pFC, g_fcp);

    pack_kernel<<<(PACK_TOTAL + 255) / 256, 256>>>(w0, w1, fcw, pW0, pW1, pFC);

    dim3 gU(1024 / BN, M_ / BM);  // (8, 256)
    for (int n = 0; n < 2; n++)
        gemm_f32x2<<<gU, 256>>>(x, pW0 + (size_t)n * 256 * 1024,
                                pU + (size_t)n * M_ * 1024, nullptr,
                                /*K=*/256, /*N=*/1024, /*ldc=*/1024, /*xmode=*/1);

    sru_scan<<<64, 256>>>(pU, wc0, bb0, pH0);

    for (int n = 0; n < 2; n++)
        gemm_f32x2<<<gU, 256>>>(pH0, pW1 + (size_t)n * 512 * 1024,
                                pU + (size_t)n * M_ * 1024, nullptr,
                                /*K=*/512, /*N=*/1024, /*ldc=*/1024, /*xmode=*/0);

    sru_scan<<<64, 256>>>(pU, wc1, bb1, pH1);

    dim3 gF(256 / BN, M_ / BM);   // (2, 256)
    gemm_f32x2<<<gF, 256>>>(pH1, pFC, pY, fcb,
                            /*K=*/512, /*N=*/256, /*ldc=*/256, /*xmode=*/0);

    head_kernel<<<M_ / 8, 256>>>(pY, lpw, lpb, out);
}

// round 8
// speedup vs baseline: 1.0004x; 1.0004x over previous
#include <cuda_runtime.h>
#include <cstdint>

// Problem dims (fixed by the dataset)
#define T_   1024
#define B_   32
#define DIN_ 256
#define H_   256
#define AA_  21
#define M_   (T_*B_)   // 32768

// ---------------------------------------------------------------------------
// Scratch (device globals — no cudaMalloc allowed)
// ---------------------------------------------------------------------------
__device__ float g_U  [2u*32768u*1024u];  // per-dir U tensor [n][m][h*4+k], reused L0/L1 (268MB)
__device__ float g_h0 [32768u*512u];      // layer0 output  [m][dir*H + h]
__device__ float g_h1 [32768u*512u];      // layer1 output
__device__ float g_y  [32768u*256u];      // fc1 output
__device__ float g_w0p[2*256*1024];       // packed w_l0: [n][d][h*4+k]
__device__ float g_w1p[2*512*1024];       // packed w_l1
__device__ float g_fcp[512*256];          // packed fc1_w: [k][j]

// ---------------------------------------------------------------------------
// Weight packing (cheap, re-run every launch for determinism)
// ---------------------------------------------------------------------------
#define PACK_S0 (2*256*1024)
#define PACK_S1 (2*512*1024)
#define PACK_S2 (512*256)
#define PACK_TOTAL (PACK_S0 + PACK_S1 + PACK_S2)

__global__ void pack_kernel(const float* __restrict__ w0,
                            const float* __restrict__ w1,
                            const float* __restrict__ fcw,
                            float* __restrict__ w0p,
                            float* __restrict__ w1p,
                            float* __restrict__ fcp)
{
    int i = blockIdx.x * blockDim.x + threadIdx.x;
    if (i < PACK_S0) {
        int c = i & 1023, d = (i >> 10) & 255, n = i >> 18;
        int k = c & 3, h = c >> 2;
        w0p[i] = w0[((d*2 + n)*4 + k)*H_ + h];
        return;
    }
    int j = i - PACK_S0;
    if (j < PACK_S1) {
        int c = j & 1023, d = (j >> 10) & 511, n = j >> 19;
        int k = c & 3, h = c >> 2;
        w1p[j] = w1[((d*2 + n)*4 + k)*H_ + h];
        return;
    }
    int l = j - PACK_S1;
    if (l < PACK_S2) {
        int jj = l & 255, kk = l >> 8;
        fcp[l] = fcw[jj*512 + kk];
    }
}

// ---------------------------------------------------------------------------
// FP32 GEMM with packed fma.rn.f32x2 (Blackwell FFMA2, 2x FFMA throughput).
// C[m][c] = sum_k A[m][k] * B[k][c]  (+ optional bias[c])
// A row access: xmode=1 -> A is x (B,T,DIN) with m = t*B + b; else contiguous ld=K.
// Block tile 128x128, BK=16, 256 threads, 8x8 micro-tile / thread.
// A is stored DUPLICATED into SMEM as float2(a,a) so the inner loop is pure
// LDS.64 + FFMA2 (no mov.b64 packing on the critical path).
// ---------------------------------------------------------------------------
#define BM 128
#define BN 128
#define BK 16

__global__ void __launch_bounds__(256)
gemm_f32x2(const float* __restrict__ A, const float* __restrict__ Bm,
           float* __restrict__ C, const float* __restrict__ bias,
           int K, int N, int ldc, int xmode)
{
    __shared__ __align__(16) float2 As2[BK][BM];  // 16KB (duplicated pairs)
    __shared__ __align__(16) float  Bs [BK][BN];  // 8KB

    const int tid = threadIdx.x;
    const int m0  = blockIdx.y * BM;
    const int n0  = blockIdx.x * BN;
    const int rg  = tid >> 4;   // 0..15 : row group (8 rows each)
    const int cg  = tid & 15;   // 0..15 : col group (8 cols each)

    unsigned long long acc[8][4];
#pragma unroll
    for (int i = 0; i < 8; i++)
#pragma unroll
        for (int p = 0; p < 4; p++) acc[i][p] = 0ull;

    for (int kt = 0; kt < K; kt += BK) {
        // --- load A tile (128 x 16), duplicate into (a,a) pairs, layout [k][m]
#pragma unroll
        for (int q = 0; q < 2; q++) {
            int f  = (tid << 1) + q;      // 0..511 float4 slots
            int ml = f >> 2;              // 0..127
            int k4 = (f & 3) << 2;        // 0,4,8,12
            int m  = m0 + ml;
            const float* ap;
            if (xmode) {
                int t = m >> 5, b = m & 31;             // m = t*B + b, B=32
                ap = A + ((size_t)b * T_ + t) * DIN_ + kt + k4;
            } else {
                ap = A + (size_t)m * K + kt + k4;
            }
            float4 v = *(const float4*)ap;
            As2[k4 + 0][ml] = make_float2(v.x, v.x);
            As2[k4 + 1][ml] = make_float2(v.y, v.y);
            As2[k4 + 2][ml] = make_float2(v.z, v.z);
            As2[k4 + 3][ml] = make_float2(v.w, v.w);
        }
        // --- load B tile (16 x 128)
#pragma unroll
        for (int q = 0; q < 2; q++) {
            int f  = (tid << 1) + q;
            int kl = f >> 5;              // 0..15
            int n4 = (f & 31) << 2;       // 0..124
            *(float4*)&Bs[kl][n4] =
                *(const float4*)(Bm + (size_t)(kt + kl) * N + n0 + n4);
        }
        __syncthreads();

#pragma unroll
        for (int kk = 0; kk < BK; kk++) {
            unsigned long long a[8], bq[4];
#pragma unroll
            for (int i = 0; i < 8; i++)
                a[i] = *(const unsigned long long*)&As2[kk][rg * 8 + i];
            const unsigned long long* bp =
                (const unsigned long long*)&Bs[kk][cg * 8];
#pragma unroll
            for (int p = 0; p < 4; p++) bq[p] = bp[p];
#pragma unroll
            for (int i = 0; i < 8; i++)
#pragma unroll
                for (int p = 0; p < 4; p++)
                    asm("fma.rn.f32x2 %0, %1, %2, %0;"
                        : "+l"(acc[i][p]) : "l"(a[i]), "l"(bq[p]));
        }
        __syncthreads();
    }

    // --- epilogue
#pragma unroll
    for (int i = 0; i < 8; i++) {
        int m = m0 + rg * 8 + i;
        float o[8];
#pragma unroll
        for (int p = 0; p < 4; p++) {
            o[2*p]   = __uint_as_float((unsigned)(acc[i][p] & 0xffffffffull));
            o[2*p+1] = __uint_as_float((unsigned)(acc[i][p] >> 32));
        }
        if (bias) {
#pragma unroll
            for (int j = 0; j < 8; j++) o[j] += bias[n0 + cg * 8 + j];
        }
        float4* cp = (float4*)(C + (size_t)m * ldc + n0 + cg * 8);
        cp[0] = make_float4(o[0], o[1], o[2], o[3]);
        cp[1] = make_float4(o[4], o[5], o[6], o[7]);
    }
}

// ---------------------------------------------------------------------------
// SRU recurrence: one thread per (dir, b, h) lane, 1024 sequential steps.
//   f = sigma(u1 + vf*c + bf); c' = f*c + (1-f)*u0
//   r = sigma(u2 + vr*c + br); h = r*c' + (1-r)*u3      (r uses OLD c)
// U layout per dir: [m = t*B+b][h*4 + k] -> float4 per (m,h).
// Output: Hout[m][dir*H + h].
// ---------------------------------------------------------------------------
__device__ __forceinline__ float sigm_(float x)
{
    return __fdividef(1.0f, 1.0f + __expf(-x));
}

__global__ void __launch_bounds__(256)
sru_scan(const float* __restrict__ U, const float* __restrict__ wc,
         const float* __restrict__ bb, float* __restrict__ Hout)
{
    int g   = blockIdx.x * blockDim.x + threadIdx.x;  // 0..16383
    int dir = g >> 13;
    int e   = g & 8191;
    int h   = e & 255;
    int b   = e >> 8;

    const float vf = wc[(dir*2 + 0)*H_ + h];
    const float vr = wc[(dir*2 + 1)*H_ + h];
    const float bf = bb[(dir*2 + 0)*H_ + h];
    const float br = bb[(dir*2 + 1)*H_ + h];

    const float4* Ud = (const float4*)(U + (size_t)dir * M_ * 1024u);
    float c = 0.0f;

    if (dir == 0) {
        for (int t = 0; t < T_; t++) {
            float4 u = Ud[(size_t)(t * B_ + b) * 256 + h];
            float f = sigm_(u.y + __fmaf_rn(vf, c, bf));
            float r = sigm_(u.z + __fmaf_rn(vr, c, br));
            c = __fmaf_rn(f, c - u.x, u.x);
            float hv = __fmaf_rn(r, c - u.w, u.w);
            Hout[(size_t)(t * B_ + b) * 512 + h] = hv;
        }
    } else {
        for (int t = T_ - 1; t >= 0; t--) {
            float4 u = Ud[(size_t)(t * B_ + b) * 256 + h];
            float f = sigm_(u.y + __fmaf_rn(vf, c, bf));
            float r = sigm_(u.z + __fmaf_rn(vr, c, br));
            c = __fmaf_rn(f, c - u.x, u.x);
            float hv = __fmaf_rn(r, c - u.w, u.w);
            Hout[(size_t)(t * B_ + b) * 512 + H_ + h] = hv;
        }
    }
}

// ---------------------------------------------------------------------------
// Head: logits = y @ lp_w^T + lp_b (K=256, N=21), then log_softmax over 21.
// One warp per row m. lp_w cached in SMEM. Output (B,T,AA): m = t*B + b.
// ---------------------------------------------------------------------------
__global__ void __launch_bounds__(256)
head_kernel(const float* __restrict__ Y, const float* __restrict__ lpw,
            const float* __restrict__ lpb, float* __restrict__ out)
{
    __shared__ float sw[AA_ * 256];
    for (int i = threadIdx.x; i < AA_ * 256; i += blockDim.x) sw[i] = lpw[i];
    __syncthreads();

    int warp = (blockIdx.x * blockDim.x + threadIdx.x) >> 5;
    int lane = threadIdx.x & 31;
    if (warp >= M_) return;

    const float* y = Y + (size_t)warp * 256;
    float yv[8];
#pragma unroll
    for (int i = 0; i < 8; i++) yv[i] = y[lane + 32 * i];

    float logit = 0.0f;
#pragma unroll
    for (int a = 0; a < AA_; a++) {
        float s = 0.0f;
#pragma unroll
        for (int i = 0; i < 8; i++) s += yv[i] * sw[a * 256 + lane + 32 * i];
#pragma unroll
        for (int o = 16; o; o >>= 1) s += __shfl_xor_sync(0xffffffffu, s, o);
        if (lane == a) logit = s;
    }

    float v = (lane < AA_) ? (logit + lpb[lane]) : -3.402823466e+38f;
    float mx = v;
#pragma unroll
    for (int o = 16; o; o >>= 1)
        mx = fmaxf(mx, __shfl_xor_sync(0xffffffffu, mx, o));
    float ev = (lane < AA_) ? __expf(v - mx) : 0.0f;
    float se = ev;
#pragma unroll
    for (int o = 16; o; o >>= 1) se += __shfl_xor_sync(0xffffffffu, se, o);
    float ls = __logf(se);

    if (lane < AA_) {
        int m = warp, t = m >> 5, b = m & 31;
        out[(size_t)b * T_ * AA_ + t * AA_ + lane] = v - mx - ls;
    }
}

// ---------------------------------------------------------------------------
// Launch: pack -> GEMM U0 (x2 dirs) -> scan0 -> GEMM U1 (x2) -> scan1
//         -> FC1 GEMM (+bias) -> head. All on default stream (capturable).
// ---------------------------------------------------------------------------
extern "C" void kernel_launch(void* const* d_in, const int* in_sizes, int n_in,
                              void* d_out, int out_size)
{
    const float* x   = (const float*)d_in[0];
    // d_in[1] = hidden (unused, as in reference)
    const float* w0  = (const float*)d_in[2];
    const float* wc0 = (const float*)d_in[3];
    const float* bb0 = (const float*)d_in[4];
    const float* w1  = (const float*)d_in[5];
    const float* wc1 = (const float*)d_in[6];
    const float* bb1 = (const float*)d_in[7];
    const float* fcw = (const float*)d_in[8];
    const float* fcb = (const float*)d_in[9];
    const float* lpw = (const float*)d_in[10];
    const float* lpb = (const float*)d_in[11];
    float* out = (float*)d_out;

    float *pU, *pH0, *pH1, *pY, *pW0, *pW1, *pFC;
    cudaGetSymbolAddress((void**)&pU,  g_U);
    cudaGetSymbolAddress((void**)&pH0, g_h0);
    cudaGetSymbolAddress((void**)&pH1, g_h1);
    cudaGetSymbolAddress((void**)&pY,  g_y);
    cudaGetSymbolAddress((void**)&pW0, g_w0p);
    cudaGetSymbolAddress((void**)&pW1, g_w1p);
    cudaGetSymbolAddress((void**)&pFC, g_fcp);

    pack_kernel<<<(PACK_TOTAL + 255) / 256, 256>>>(w0, w1, fcw, pW0, pW1, pFC);

    dim3 gU(1024 / BN, M_ / BM);  // (8, 256)
    for (int n = 0; n < 2; n++)
        gemm_f32x2<<<gU, 256>>>(x, pW0 + (size_t)n * 256 * 1024,
                                pU + (size_t)n * M_ * 1024, nullptr,
                                /*K=*/256, /*N=*/1024, /*ldc=*/1024, /*xmode=*/1);

    sru_scan<<<64, 256>>>(pU, wc0, bb0, pH0);

    for (int n = 0; n < 2; n++)
        gemm_f32x2<<<gU, 256>>>(pH0, pW1 + (size_t)n * 512 * 1024,
                                pU + (size_t)n * M_ * 1024, nullptr,
                                /*K=*/512, /*N=*/1024, /*ldc=*/1024, /*xmode=*/0);

    sru_scan<<<64, 256>>>(pU, wc1, bb1, pH1);

    dim3 gF(256 / BN, M_ / BM);   // (2, 256)
    gemm_f32x2<<<gF, 256>>>(pH1, pFC, pY, fcb,
                            /*K=*/512, /*N=*/256, /*ldc=*/256, /*xmode=*/0);

    head_kernel<<<M_ / 8, 256>>>(pY, lpw, lpb, out);
}

// round 14
// speedup vs baseline: 2.3355x; 2.3345x over previous
#include <cuda_runtime.h>
#include <cuda_bf16.h>
#include <cstdint>

// Problem dims
#define T_   1024
#define B_   32
#define DIN_ 256
#define H_   256
#define AA_  21
#define M_   (T_*B_)   // 32768

// ---------------------------------------------------------------------------
// Device scratch (no cudaMalloc allowed)
// ---------------------------------------------------------------------------
__device__ float g_U [2u*32768u*1024u];          // GEMM U output per dir (fp32)
__device__ float g_y [32768u*256u];              // fc1 output (fp32)

// bf16 hi/lo operands, plain row-major [rows][K]
__device__ __nv_bfloat16 g_A0h[32768u*256u], g_A0l[32768u*256u];   // x rows m=t*B+b
__device__ __nv_bfloat16 g_A1h[32768u*512u], g_A1l[32768u*512u];   // scan0 out
__device__ __nv_bfloat16 g_A2h[32768u*512u], g_A2l[32768u*512u];   // scan1 out
__device__ __nv_bfloat16 g_B0h[2u*1024u*256u], g_B0l[2u*1024u*256u];
__device__ __nv_bfloat16 g_B1h[2u*1024u*512u], g_B1l[2u*1024u*512u];
__device__ __nv_bfloat16 g_FCh[256u*512u],     g_FCl[256u*512u];

// ---------------------------------------------------------------------------
// Helpers
// ---------------------------------------------------------------------------
__device__ __forceinline__ uint32_t smem_u32(const void* p) {
    uint32_t a;
    asm("{ .reg .u64 t; cvta.to.shared.u64 t, %1; cvt.u32.u64 %0, t; }"
        : "=r"(a) : "l"(p));
    return a;
}
__device__ __forceinline__ void cp16(uint32_t dst, const void* src) {
    asm volatile("cp.async.cg.shared.global [%0], [%1], 16;"
                 :: "r"(dst), "l"(src));
}
__device__ __forceinline__ void ldsm4(uint32_t* r, uint32_t a) {
    asm volatile("ldmatrix.sync.aligned.m8n8.x4.shared.b16 {%0,%1,%2,%3}, [%4];"
                 : "=r"(r[0]), "=r"(r[1]), "=r"(r[2]), "=r"(r[3]) : "r"(a));
}
__device__ __forceinline__ void mma16816(float* c, const uint32_t* a,
                                         const uint32_t* b) {
    asm volatile("mma.sync.aligned.m16n8k16.row.col.f32.bf16.bf16.f32 "
                 "{%0,%1,%2,%3}, {%4,%5,%6,%7}, {%8,%9}, {%0,%1,%2,%3};"
                 : "+f"(c[0]), "+f"(c[1]), "+f"(c[2]), "+f"(c[3])
                 : "r"(a[0]), "r"(a[1]), "r"(a[2]), "r"(a[3]),
                   "r"(b[0]), "r"(b[1]));
}
__device__ __forceinline__ void split_store(__nv_bfloat16* hi, __nv_bfloat16* lo,
                                            size_t off, float v) {
    __nv_bfloat16 h = __float2bfloat16(v);
    hi[off] = h;
    lo[off] = __float2bfloat16(v - __bfloat162float(h));
}

// ---------------------------------------------------------------------------
// Weight pack: fp32 weights -> bf16 hi/lo row-major B matrices [n_out][k]
// ---------------------------------------------------------------------------
#define PK_S0 (2*1024*256)
#define PK_S1 (2*1024*512)
#define PK_S2 (256*512)
#define PK_TOT (PK_S0 + PK_S1 + PK_S2)

__global__ void pack_weights(const float* __restrict__ w0,
                             const float* __restrict__ w1,
                             const float* __restrict__ fcw)
{
    int i = blockIdx.x * blockDim.x + threadIdx.x;
    if (i < PK_S0) {
        int n = i / 262144, r = i % 262144;
        int c = r >> 8, d = r & 255;               // row c = h*4+k, col d
        int k = c & 3, h = c >> 2;
        float v = w0[((d*2 + n)*4 + k)*H_ + h];
        split_store(g_B0h, g_B0l, (size_t)i, v);   // off = n*262144 + c*256 + d
        return;
    }
    int j = i - PK_S0;
    if (j < PK_S1) {
        int n = j / 524288, r = j % 524288;
        int c = r >> 9, d = r & 511;
        int k = c & 3, h = c >> 2;
        float v = w1[((d*2 + n)*4 + k)*H_ + h];
        split_store(g_B1h, g_B1l, (size_t)j, v);
        return;
    }
    int l = j - PK_S1;
    if (l < PK_S2) {                               // fc1_w is (H,2H) row-major already
        split_store(g_FCh, g_FCl, (size_t)l, fcw[l]);
    }
}

// ---------------------------------------------------------------------------
// x (B,T,DIN) fp32 -> row-major bf16 hi/lo A0 with row m = t*B + b
// ---------------------------------------------------------------------------
__global__ void convert_x(const float* __restrict__ x)
{
    int id = blockIdx.x * blockDim.x + threadIdx.x;   // < 32768*64
    int m = id >> 6, q = id & 63;
    int b = m & 31, t = m >> 5;
    float4 v = ((const float4*)x)[(size_t)(b * T_ + t) * 64 + q];
    size_t off = (size_t)m * 256 + (q << 2);
    __nv_bfloat16 h0 = __float2bfloat16(v.x), h1 = __float2bfloat16(v.y);
    __nv_bfloat16 h2 = __float2bfloat16(v.z), h3 = __float2bfloat16(v.w);
    ushort4 hs = make_ushort4(__bfloat16_as_ushort(h0), __bfloat16_as_ushort(h1),
                              __bfloat16_as_ushort(h2), __bfloat16_as_ushort(h3));
    ushort4 ls = make_ushort4(
        __bfloat16_as_ushort(__float2bfloat16(v.x - __bfloat162float(h0))),
        __bfloat16_as_ushort(__float2bfloat16(v.y - __bfloat162float(h1))),
        __bfloat16_as_ushort(__float2bfloat16(v.z - __bfloat162float(h2))),
        __bfloat16_as_ushort(__float2bfloat16(v.w - __bfloat162float(h3))));
    *(ushort4*)(g_A0h + off) = hs;
    *(ushort4*)(g_A0l + off) = ls;
}

// ---------------------------------------------------------------------------
// bf16x3-split GEMM on mma.sync (HMMA): C[m][c] = sum_k A[m][k]*B[c][k]
// Block 128x128xBK32, 256 thr, 8 warps (warp tile 32x64), cp.async 3-stage.
// SMEM tile rows padded to 40 bf16 (80B) -> conflict-free ldmatrix.
// ---------------------------------------------------------------------------
#define TILE_B   10240          // 128 rows * 80 bytes
#define STAGE_B  (4*TILE_B)     // Ah, Al, Bh, Bl
#define NSTAGE   3
#define GEMM_SMEM (NSTAGE*STAGE_B)

__device__ __forceinline__ void load_stage(uint32_t st,
    const __nv_bfloat16* gAh, const __nv_bfloat16* gAl,
    const __nv_bfloat16* gBh, const __nv_bfloat16* gBl,
    int K, int kt, int tid)
{
    const __nv_bfloat16* base[4] = {gAh, gAl, gBh, gBl};
#pragma unroll
    for (int tl = 0; tl < 4; tl++) {
        uint32_t doff = st + tl * TILE_B;
#pragma unroll
        for (int i = 0; i < 2; i++) {
            int q = tid + i * 256;           // 512 16B chunks per tile
            int row = q >> 2, c16 = q & 3;
            cp16(doff + row * 80 + c16 * 16,
                 base[tl] + (size_t)row * K + kt * 32 + c16 * 8);
        }
    }
}

__global__ void __launch_bounds__(256, 1)
gemm_mma(const __nv_bfloat16* __restrict__ Ah, const __nv_bfloat16* __restrict__ Al,
         const __nv_bfloat16* __restrict__ Bh, const __nv_bfloat16* __restrict__ Bl,
         float* __restrict__ C, const float* __restrict__ bias, int K, int ldc)
{
    extern __shared__ char smem[];
    const uint32_t sb = smem_u32(smem);
    const int tid = threadIdx.x;
    const int lane = tid & 31, wid = tid >> 5;
    const int wm = wid & 3, wn = wid >> 2;    // 4 x 2 warp grid

    const __nv_bfloat16* gAh = Ah + (size_t)blockIdx.y * 128 * K;
    const __nv_bfloat16* gAl = Al + (size_t)blockIdx.y * 128 * K;
    const __nv_bfloat16* gBh = Bh + (size_t)blockIdx.x * 128 * K;
    const __nv_bfloat16* gBl = Bl + (size_t)blockIdx.x * 128 * K;

    // ldmatrix per-thread byte offsets within a tile
    uint32_t aoff[2], boff[4];
#pragma unroll
    for (int mt = 0; mt < 2; mt++) {
        int row = wm * 32 + mt * 16 + (lane & 15);
        aoff[mt] = row * 80 + ((lane >> 4) & 1) * 16;
    }
#pragma unroll
    for (int p = 0; p < 4; p++) {
        int row = wn * 64 + p * 16 + ((lane >> 4) & 1) * 8 + (lane & 7);
        boff[p] = row * 80 + ((lane >> 3) & 1) * 16;
    }

    float acc[2][8][4];
#pragma unroll
    for (int a = 0; a < 2; a++)
#pragma unroll
        for (int b = 0; b < 8; b++)
#pragma unroll
            for (int c = 0; c < 4; c++) acc[a][b][c] = 0.0f;

    const int KT = K >> 5;
    load_stage(sb, gAh, gAl, gBh, gBl, K, 0, tid);
    asm volatile("cp.async.commit_group;");
    load_stage(sb + STAGE_B, gAh, gAl, gBh, gBl, K, 1, tid);
    asm volatile("cp.async.commit_group;");

    for (int kt = 0; kt < KT; kt++) {
        asm volatile("cp.async.wait_group 1;");
        __syncthreads();
        uint32_t st = sb + (kt % NSTAGE) * STAGE_B;
        uint32_t s_ah = st, s_al = st + TILE_B;
        uint32_t s_bh = st + 2*TILE_B, s_bl = st + 3*TILE_B;
#pragma unroll
        for (int kk = 0; kk < 2; kk++) {
            uint32_t ah[2][4], al[2][4];
#pragma unroll
            for (int mt = 0; mt < 2; mt++) {
                ldsm4(ah[mt], s_ah + aoff[mt] + kk * 32);
                ldsm4(al[mt], s_al + aoff[mt] + kk * 32);
            }
#pragma unroll
            for (int p = 0; p < 4; p++) {
                uint32_t bh[4], bl[4];
                ldsm4(bh, s_bh + boff[p] + kk * 32);
                ldsm4(bl, s_bl + boff[p] + kk * 32);
#pragma unroll
                for (int mt = 0; mt < 2; mt++) {
                    mma16816(acc[mt][2*p],   ah[mt], bh);
                    mma16816(acc[mt][2*p],   ah[mt], bl);
                    mma16816(acc[mt][2*p],   al[mt], bh);
                    mma16816(acc[mt][2*p+1], ah[mt], bh + 2);
                    mma16816(acc[mt][2*p+1], ah[mt], bl + 2);
                    mma16816(acc[mt][2*p+1], al[mt], bh + 2);
                }
            }
        }
        __syncthreads();
        if (kt + 2 < KT)
            load_stage(sb + ((kt + 2) % NSTAGE) * STAGE_B,
                       gAh, gAl, gBh, gBl, K, kt + 2, tid);
        asm volatile("cp.async.commit_group;");
    }

    // epilogue: c0,c1 -> (m, n..n+1); c2,c3 -> (m+8, n..n+1)
    const int mbase = blockIdx.y * 128 + wm * 32;
    const int nbase = blockIdx.x * 128 + wn * 64;
#pragma unroll
    for (int mt = 0; mt < 2; mt++) {
        int m = mbase + mt * 16 + (lane >> 2);
#pragma unroll
        for (int nj = 0; nj < 8; nj++) {
            int n = nbase + nj * 8 + (lane & 3) * 2;
            float b0 = 0.0f, b1 = 0.0f;
            if (bias) { b0 = bias[n]; b1 = bias[n + 1]; }
            float2 v0 = make_float2(acc[mt][nj][0] + b0, acc[mt][nj][1] + b1);
            float2 v1 = make_float2(acc[mt][nj][2] + b0, acc[mt][nj][3] + b1);
            *(float2*)(C + (size_t)m * ldc + n)       = v0;
            *(float2*)(C + (size_t)(m + 8) * ldc + n) = v1;
        }
    }
}

// ---------------------------------------------------------------------------
// SRU recurrence: one thread per (dir,b,h), 1024 sequential steps, 8-deep
// prefetch. 256 blocks x 64 threads -> covers all SMs. Writes next layer's
// A operand directly as bf16 hi/lo, row-major [m][512], col = dir*256+h.
// ---------------------------------------------------------------------------
__device__ __forceinline__ float sigm_(float x) {
    return __fdividef(1.0f, 1.0f + __expf(-x));
}

__global__ void __launch_bounds__(64)
sru_scan(const float* __restrict__ U, const float* __restrict__ wc,
         const float* __restrict__ bb,
         __nv_bfloat16* __restrict__ Ohi, __nv_bfloat16* __restrict__ Olo)
{
    int g   = blockIdx.x * 64 + threadIdx.x;   // 0..16383
    int dir = g >> 13;
    int e   = g & 8191;
    int h   = e & 255;
    int b   = e >> 8;

    const float vf = wc[(dir*2 + 0)*H_ + h];
    const float vr = wc[(dir*2 + 1)*H_ + h];
    const float bf = bb[(dir*2 + 0)*H_ + h];
    const float br = bb[(dir*2 + 1)*H_ + h];

    const float4* Ud = (const float4*)(U + (size_t)dir * M_ * 1024u);
    const int colg = dir * 256 + h;

    float c = 0.0f;
    float4 pf[8];
#pragma unroll
    for (int i = 0; i < 8; i++) {
        int tp = dir ? (T_ - 1 - i) : i;
        pf[i] = Ud[(size_t)(tp * B_ + b) * 256 + h];
    }

    for (int t = 0; t < T_; t += 8) {
#pragma unroll
        for (int j = 0; j < 8; j++) {
            float4 u = pf[j];
            int tn = t + 8 + j;
            if (tn < T_) {
                int tp = dir ? (T_ - 1 - tn) : tn;
                pf[j] = Ud[(size_t)(tp * B_ + b) * 256 + h];
            }
            float f = sigm_(u.y + __fmaf_rn(vf, c, bf));
            float r = sigm_(u.z + __fmaf_rn(vr, c, br));
            c = __fmaf_rn(f, c - u.x, u.x);
            float hv = __fmaf_rn(r, c - u.w, u.w);

            int tcur = t + j;
            int tp = dir ? (T_ - 1 - tcur) : tcur;
            size_t off = (size_t)(tp * B_ + b) * 512 + colg;
            split_store(Ohi, Olo, off, hv);
        }
    }
}

// ---------------------------------------------------------------------------
// Head: logits = y @ lp_w^T + lp_b (K=256, N=21), then log_softmax over 21.
// One warp per row m. Output (B,T,AA): m = t*B + b.
// ---------------------------------------------------------------------------
__global__ void __launch_bounds__(256)
head_kernel(const float* __restrict__ Y, const float* __restrict__ lpw,
            const float* __restrict__ lpb, float* __restrict__ out)
{
    __shared__ float sw[AA_ * 256];
    for (int i = threadIdx.x; i < AA_ * 256; i += blockDim.x) sw[i] = lpw[i];
    __syncthreads();

    int warp = (blockIdx.x * blockDim.x + threadIdx.x) >> 5;
    int lane = threadIdx.x & 31;
    if (warp >= M_) return;

    const float* y = Y + (size_t)warp * 256;
    float yv[8];
#pragma unroll
    for (int i = 0; i < 8; i++) yv[i] = y[lane + 32 * i];

    float logit = 0.0f;
#pragma unroll
    for (int a = 0; a < AA_; a++) {
        float s = 0.0f;
#pragma unroll
        for (int i = 0; i < 8; i++) s += yv[i] * sw[a * 256 + lane + 32 * i];
#pragma unroll
        for (int o = 16; o; o >>= 1) s += __shfl_xor_sync(0xffffffffu, s, o);
        if (lane == a) logit = s;
    }

    float v = (lane < AA_) ? (logit + lpb[lane]) : -3.402823466e+38f;
    float mx = v;
#pragma unroll
    for (int o = 16; o; o >>= 1)
        mx = fmaxf(mx, __shfl_xor_sync(0xffffffffu, mx, o));
    float ev = (lane < AA_) ? __expf(v - mx) : 0.0f;
    float se = ev;
#pragma unroll
    for (int o = 16; o; o >>= 1) se += __shfl_xor_sync(0xffffffffu, se, o);
    float ls = __logf(se);

    if (lane < AA_) {
        int m = warp, t = m >> 5, b = m & 31;
        out[(size_t)b * T_ * AA_ + t * AA_ + lane] = v - mx - ls;
    }
}

// ---------------------------------------------------------------------------
// Launch
// ---------------------------------------------------------------------------
extern "C" void kernel_launch(void* const* d_in, const int* in_sizes, int n_in,
                              void* d_out, int out_size)
{
    const float* x   = (const float*)d_in[0];
    const float* w0  = (const float*)d_in[2];
    const float* wc0 = (const float*)d_in[3];
    const float* bb0 = (const float*)d_in[4];
    const float* w1  = (const float*)d_in[5];
    const float* wc1 = (const float*)d_in[6];
    const float* bb1 = (const float*)d_in[7];
    const float* fcw = (const float*)d_in[8];
    const float* fcb = (const float*)d_in[9];
    const float* lpw = (const float*)d_in[10];
    const float* lpb = (const float*)d_in[11];
    float* out = (float*)d_out;

    float *pU, *pY;
    __nv_bfloat16 *pA0h,*pA0l,*pA1h,*pA1l,*pA2h,*pA2l,*pB0h,*pB0l,*pB1h,*pB1l,*pFh,*pFl;
    cudaGetSymbolAddress((void**)&pU,   g_U);
    cudaGetSymbolAddress((void**)&pY,   g_y);
    cudaGetSymbolAddress((void**)&pA0h, g_A0h); cudaGetSymbolAddress((void**)&pA0l, g_A0l);
    cudaGetSymbolAddress((void**)&pA1h, g_A1h); cudaGetSymbolAddress((void**)&pA1l, g_A1l);
    cudaGetSymbolAddress((void**)&pA2h, g_A2h); cudaGetSymbolAddress((void**)&pA2l, g_A2l);
    cudaGetSymbolAddress((void**)&pB0h, g_B0h); cudaGetSymbolAddress((void**)&pB0l, g_B0l);
    cudaGetSymbolAddress((void**)&pB1h, g_B1h); cudaGetSymbolAddress((void**)&pB1l, g_B1l);
    cudaGetSymbolAddress((void**)&pFh,  g_FCh); cudaGetSymbolAddress((void**)&pFl,  g_FCl);

    cudaFuncSetAttribute(gemm_mma, cudaFuncAttributeMaxDynamicSharedMemorySize,
                         GEMM_SMEM);

    pack_weights<<<(PK_TOT + 255) / 256, 256>>>(w0, w1, fcw);
    convert_x<<<(32768 * 64) / 256, 256>>>(x);

    // Layer 0: U[n] = A0 (32768x256) * B0[n]^T (1024x256)
    dim3 gU(8, 256);
    for (int n = 0; n < 2; n++)
        gemm_mma<<<gU, 256, GEMM_SMEM>>>(pA0h, pA0l,
            pB0h + (size_t)n * 262144, pB0l + (size_t)n * 262144,
            pU + (size_t)n * M_ * 1024, nullptr, /*K=*/256, /*ldc=*/1024);

    sru_scan<<<256, 64>>>(pU, wc0, bb0, pA1h, pA1l);

    // Layer 1: K=512
    for (int n = 0; n < 2; n++)
        gemm_mma<<<gU, 256, GEMM_SMEM>>>(pA1h, pA1l,
            pB1h + (size_t)n * 524288, pB1l + (size_t)n * 524288,
            pU + (size_t)n * M_ * 1024, nullptr, /*K=*/512, /*ldc=*/1024);

    sru_scan<<<256, 64>>>(pU, wc1, bb1, pA2h, pA2l);

    // FC1: (32768x512) * (256x512)^T + bias
    dim3 gF(2, 256);
    gemm_mma<<<gF, 256, GEMM_SMEM>>>(pA2h, pA2l, pFh, pFl, pY, fcb,
                                     /*K=*/512, /*ldc=*/256);

    head_kernel<<<M_ / 8, 256>>>(pY, lpw, lpb, out);
}

// round 15
// speedup vs baseline: 2.3356x; 1.0000x over previous
#include <cuda_runtime.h>
#include <cuda_bf16.h>
#include <cstdint>

// Problem dims
#define T_   1024
#define B_   32
#define DIN_ 256
#define H_   256
#define AA_  21
#define M_   (T_*B_)   // 32768

// ---------------------------------------------------------------------------
// Device scratch (no cudaMalloc allowed)
// ---------------------------------------------------------------------------
__device__ float g_U [2u*32768u*1024u];          // GEMM U output per dir (fp32)
__device__ float g_y [32768u*256u];              // fc1 output (fp32)

// bf16 hi/lo operands, plain row-major [rows][K]
__device__ __nv_bfloat16 g_A0h[32768u*256u], g_A0l[32768u*256u];   // x rows m=t*B+b
__device__ __nv_bfloat16 g_A1h[32768u*512u], g_A1l[32768u*512u];   // scan0 out
__device__ __nv_bfloat16 g_A2h[32768u*512u], g_A2l[32768u*512u];   // scan1 out
__device__ __nv_bfloat16 g_B0h[2u*1024u*256u], g_B0l[2u*1024u*256u];
__device__ __nv_bfloat16 g_B1h[2u*1024u*512u], g_B1l[2u*1024u*512u];
__device__ __nv_bfloat16 g_FCh[256u*512u],     g_FCl[256u*512u];

// ---------------------------------------------------------------------------
// Helpers
// ---------------------------------------------------------------------------
__device__ __forceinline__ uint32_t smem_u32(const void* p) {
    uint32_t a;
    asm("{ .reg .u64 t; cvta.to.shared.u64 t, %1; cvt.u32.u64 %0, t; }"
        : "=r"(a) : "l"(p));
    return a;
}
__device__ __forceinline__ void cp16(uint32_t dst, const void* src) {
    asm volatile("cp.async.cg.shared.global [%0], [%1], 16;"
                 :: "r"(dst), "l"(src));
}
__device__ __forceinline__ void ldsm4(uint32_t* r, uint32_t a) {
    asm volatile("ldmatrix.sync.aligned.m8n8.x4.shared.b16 {%0,%1,%2,%3}, [%4];"
                 : "=r"(r[0]), "=r"(r[1]), "=r"(r[2]), "=r"(r[3]) : "r"(a));
}
__device__ __forceinline__ void mma16816(float* c, const uint32_t* a,
                                         const uint32_t* b) {
    asm volatile("mma.sync.aligned.m16n8k16.row.col.f32.bf16.bf16.f32 "
                 "{%0,%1,%2,%3}, {%4,%5,%6,%7}, {%8,%9}, {%0,%1,%2,%3};"
                 : "+f"(c[0]), "+f"(c[1]), "+f"(c[2]), "+f"(c[3])
                 : "r"(a[0]), "r"(a[1]), "r"(a[2]), "r"(a[3]),
                   "r"(b[0]), "r"(b[1]));
}
__device__ __forceinline__ void split_store(__nv_bfloat16* hi, __nv_bfloat16* lo,
                                            size_t off, float v) {
    __nv_bfloat16 h = __float2bfloat16(v);
    hi[off] = h;
    lo[off] = __float2bfloat16(v - __bfloat162float(h));
}

// ---------------------------------------------------------------------------
// Weight pack: fp32 weights -> bf16 hi/lo row-major B matrices [n_out][k]
// ---------------------------------------------------------------------------
#define PK_S0 (2*1024*256)
#define PK_S1 (2*1024*512)
#define PK_S2 (256*512)
#define PK_TOT (PK_S0 + PK_S1 + PK_S2)

__global__ void pack_weights(const float* __restrict__ w0,
                             const float* __restrict__ w1,
                             const float* __restrict__ fcw)
{
    int i = blockIdx.x * blockDim.x + threadIdx.x;
    if (i < PK_S0) {
        int n = i / 262144, r = i % 262144;
        int c = r >> 8, d = r & 255;               // row c = h*4+k, col d
        int k = c & 3, h = c >> 2;
        float v = w0[((d*2 + n)*4 + k)*H_ + h];
        split_store(g_B0h, g_B0l, (size_t)i, v);   // off = n*262144 + c*256 + d
        return;
    }
    int j = i - PK_S0;
    if (j < PK_S1) {
        int n = j / 524288, r = j % 524288;
        int c = r >> 9, d = r & 511;
        int k = c & 3, h = c >> 2;
        float v = w1[((d*2 + n)*4 + k)*H_ + h];
        split_store(g_B1h, g_B1l, (size_t)j, v);
        return;
    }
    int l = j - PK_S1;
    if (l < PK_S2) {                               // fc1_w is (H,2H) row-major already
        split_store(g_FCh, g_FCl, (size_t)l, fcw[l]);
    }
}

// ---------------------------------------------------------------------------
// x (B,T,DIN) fp32 -> row-major bf16 hi/lo A0 with row m = t*B + b
// ---------------------------------------------------------------------------
__global__ void convert_x(const float* __restrict__ x)
{
    int id = blockIdx.x * blockDim.x + threadIdx.x;   // < 32768*64
    int m = id >> 6, q = id & 63;
    int b = m & 31, t = m >> 5;
    float4 v = ((const float4*)x)[(size_t)(b * T_ + t) * 64 + q];
    size_t off = (size_t)m * 256 + (q << 2);
    __nv_bfloat16 h0 = __float2bfloat16(v.x), h1 = __float2bfloat16(v.y);
    __nv_bfloat16 h2 = __float2bfloat16(v.z), h3 = __float2bfloat16(v.w);
    ushort4 hs = make_ushort4(__bfloat16_as_ushort(h0), __bfloat16_as_ushort(h1),
                              __bfloat16_as_ushort(h2), __bfloat16_as_ushort(h3));
    ushort4 ls = make_ushort4(
        __bfloat16_as_ushort(__float2bfloat16(v.x - __bfloat162float(h0))),
        __bfloat16_as_ushort(__float2bfloat16(v.y - __bfloat162float(h1))),
        __bfloat16_as_ushort(__float2bfloat16(v.z - __bfloat162float(h2))),
        __bfloat16_as_ushort(__float2bfloat16(v.w - __bfloat162float(h3))));
    *(ushort4*)(g_A0h + off) = hs;
    *(ushort4*)(g_A0l + off) = ls;
}

// ---------------------------------------------------------------------------
// bf16x3-split GEMM on mma.sync (HMMA): C[m][c] = sum_k A[m][k]*B[c][k]
// Block 128x128xBK32, 256 thr, 8 warps (warp tile 32x64), cp.async 3-stage.
// SMEM tile rows padded to 40 bf16 (80B) -> conflict-free ldmatrix.
// ---------------------------------------------------------------------------
#define TILE_B   10240          // 128 rows * 80 bytes
#define STAGE_B  (4*TILE_B)     // Ah, Al, Bh, Bl
#define NSTAGE   3
#define GEMM_SMEM (NSTAGE*STAGE_B)

__device__ __forceinline__ void load_stage(uint32_t st,
    const __nv_bfloat16* gAh, const __nv_bfloat16* gAl,
    const __nv_bfloat16* gBh, const __nv_bfloat16* gBl,
    int K, int kt, int tid)
{
    const __nv_bfloat16* base[4] = {gAh, gAl, gBh, gBl};
#pragma unroll
    for (int tl = 0; tl < 4; tl++) {
        uint32_t doff = st + tl * TILE_B;
#pragma unroll
        for (int i = 0; i < 2; i++) {
            int q = tid + i * 256;           // 512 16B chunks per tile
            int row = q >> 2, c16 = q & 3;
            cp16(doff + row * 80 + c16 * 16,
                 base[tl] + (size_t)row * K + kt * 32 + c16 * 8);
        }
    }
}

__global__ void __launch_bounds__(256, 1)
gemm_mma(const __nv_bfloat16* __restrict__ Ah, const __nv_bfloat16* __restrict__ Al,
         const __nv_bfloat16* __restrict__ Bh, const __nv_bfloat16* __restrict__ Bl,
         float* __restrict__ C, const float* __restrict__ bias, int K, int ldc)
{
    extern __shared__ char smem[];
    const uint32_t sb = smem_u32(smem);
    const int tid = threadIdx.x;
    const int lane = tid & 31, wid = tid >> 5;
    const int wm = wid & 3, wn = wid >> 2;    // 4 x 2 warp grid

    const __nv_bfloat16* gAh = Ah + (size_t)blockIdx.y * 128 * K;
    const __nv_bfloat16* gAl = Al + (size_t)blockIdx.y * 128 * K;
    const __nv_bfloat16* gBh = Bh + (size_t)blockIdx.x * 128 * K;
    const __nv_bfloat16* gBl = Bl + (size_t)blockIdx.x * 128 * K;

    // ldmatrix per-thread byte offsets within a tile
    uint32_t aoff[2], boff[4];
#pragma unroll
    for (int mt = 0; mt < 2; mt++) {
        int row = wm * 32 + mt * 16 + (lane & 15);
        aoff[mt] = row * 80 + ((lane >> 4) & 1) * 16;
    }
#pragma unroll
    for (int p = 0; p < 4; p++) {
        int row = wn * 64 + p * 16 + ((lane >> 4) & 1) * 8 + (lane & 7);
        boff[p] = row * 80 + ((lane >> 3) & 1) * 16;
    }

    float acc[2][8][4];
#pragma unroll
    for (int a = 0; a < 2; a++)
#pragma unroll
        for (int b = 0; b < 8; b++)
#pragma unroll
            for (int c = 0; c < 4; c++) acc[a][b][c] = 0.0f;

    const int KT = K >> 5;
    load_stage(sb, gAh, gAl, gBh, gBl, K, 0, tid);
    asm volatile("cp.async.commit_group;");
    load_stage(sb + STAGE_B, gAh, gAl, gBh, gBl, K, 1, tid);
    asm volatile("cp.async.commit_group;");

    for (int kt = 0; kt < KT; kt++) {
        asm volatile("cp.async.wait_group 1;");
        __syncthreads();
        uint32_t st = sb + (kt % NSTAGE) * STAGE_B;
        uint32_t s_ah = st, s_al = st + TILE_B;
        uint32_t s_bh = st + 2*TILE_B, s_bl = st + 3*TILE_B;
#pragma unroll
        for (int kk = 0; kk < 2; kk++) {
            uint32_t ah[2][4], al[2][4];
#pragma unroll
            for (int mt = 0; mt < 2; mt++) {
                ldsm4(ah[mt], s_ah + aoff[mt] + kk * 32);
                ldsm4(al[mt], s_al + aoff[mt] + kk * 32);
            }
#pragma unroll
            for (int p = 0; p < 4; p++) {
                uint32_t bh[4], bl[4];
                ldsm4(bh, s_bh + boff[p] + kk * 32);
                ldsm4(bl, s_bl + boff[p] + kk * 32);
#pragma unroll
                for (int mt = 0; mt < 2; mt++) {
                    mma16816(acc[mt][2*p],   ah[mt], bh);
                    mma16816(acc[mt][2*p],   ah[mt], bl);
                    mma16816(acc[mt][2*p],   al[mt], bh);
                    mma16816(acc[mt][2*p+1], ah[mt], bh + 2);
                    mma16816(acc[mt][2*p+1], ah[mt], bl + 2);
                    mma16816(acc[mt][2*p+1], al[mt], bh + 2);
                }
            }
        }
        __syncthreads();
        if (kt + 2 < KT)
            load_stage(sb + ((kt + 2) % NSTAGE) * STAGE_B,
                       gAh, gAl, gBh, gBl, K, kt + 2, tid);
        asm volatile("cp.async.commit_group;");
    }

    // epilogue: c0,c1 -> (m, n..n+1); c2,c3 -> (m+8, n..n+1)
    const int mbase = blockIdx.y * 128 + wm * 32;
    const int nbase = blockIdx.x * 128 + wn * 64;
#pragma unroll
    for (int mt = 0; mt < 2; mt++) {
        int m = mbase + mt * 16 + (lane >> 2);
#pragma unroll
        for (int nj = 0; nj < 8; nj++) {
            int n = nbase + nj * 8 + (lane & 3) * 2;
            float b0 = 0.0f, b1 = 0.0f;
            if (bias) { b0 = bias[n]; b1 = bias[n + 1]; }
            float2 v0 = make_float2(acc[mt][nj][0] + b0, acc[mt][nj][1] + b1);
            float2 v1 = make_float2(acc[mt][nj][2] + b0, acc[mt][nj][3] + b1);
            *(float2*)(C + (size_t)m * ldc + n)       = v0;
            *(float2*)(C + (size_t)(m + 8) * ldc + n) = v1;
        }
    }
}

// ---------------------------------------------------------------------------
// SRU recurrence: one thread per (dir,b,h), 1024 sequential steps, 8-deep
// prefetch. 256 blocks x 64 threads -> covers all SMs. Writes next layer's
// A operand directly as bf16 hi/lo, row-major [m][512], col = dir*256+h.
// ---------------------------------------------------------------------------
__device__ __forceinline__ float sigm_(float x) {
    return __fdividef(1.0f, 1.0f + __expf(-x));
}

__global__ void __launch_bounds__(64)
sru_scan(const float* __restrict__ U, const float* __restrict__ wc,
         const float* __restrict__ bb,
         __nv_bfloat16* __restrict__ Ohi, __nv_bfloat16* __restrict__ Olo)
{
    int g   = blockIdx.x * 64 + threadIdx.x;   // 0..16383
    int dir = g >> 13;
    int e   = g & 8191;
    int h   = e & 255;
    int b   = e >> 8;

    const float vf = wc[(dir*2 + 0)*H_ + h];
    const float vr = wc[(dir*2 + 1)*H_ + h];
    const float bf = bb[(dir*2 + 0)*H_ + h];
    const float br = bb[(dir*2 + 1)*H_ + h];

    const float4* Ud = (const float4*)(U + (size_t)dir * M_ * 1024u);
    const int colg = dir * 256 + h;

    float c = 0.0f;
    float4 pf[8];
#pragma unroll
    for (int i = 0; i < 8; i++) {
        int tp = dir ? (T_ - 1 - i) : i;
        pf[i] = Ud[(size_t)(tp * B_ + b) * 256 + h];
    }

    for (int t = 0; t < T_; t += 8) {
#pragma unroll
        for (int j = 0; j < 8; j++) {
            float4 u = pf[j];
            int tn = t + 8 + j;
            if (tn < T_) {
                int tp = dir ? (T_ - 1 - tn) : tn;
                pf[j] = Ud[(size_t)(tp * B_ + b) * 256 + h];
            }
            float f = sigm_(u.y + __fmaf_rn(vf, c, bf));
            float r = sigm_(u.z + __fmaf_rn(vr, c, br));
            c = __fmaf_rn(f, c - u.x, u.x);
            float hv = __fmaf_rn(r, c - u.w, u.w);

            int tcur = t + j;
            int tp = dir ? (T_ - 1 - tcur) : tcur;
            size_t off = (size_t)(tp * B_ + b) * 512 + colg;
            split_store(Ohi, Olo, off, hv);
        }
    }
}

// ---------------------------------------------------------------------------
// Head: logits = y @ lp_w^T + lp_b (K=256, N=21), then log_softmax over 21.
// One warp per row m. Output (B,T,AA): m = t*B + b.
// ---------------------------------------------------------------------------
__global__ void __launch_bounds__(256)
head_kernel(const float* __restrict__ Y, const float* __restrict__ lpw,
            const float* __restrict__ lpb, float* __restrict__ out)
{
    __shared__ float sw[AA_ * 256];
    for (int i = threadIdx.x; i < AA_ * 256; i += blockDim.x) sw[i] = lpw[i];
    __syncthreads();

    int warp = (blockIdx.x * blockDim.x + threadIdx.x) >> 5;
    int lane = threadIdx.x & 31;
    if (warp >= M_) return;

    const float* y = Y + (size_t)warp * 256;
    float yv[8];
#pragma unroll
    for (int i = 0; i < 8; i++) yv[i] = y[lane + 32 * i];

    float logit = 0.0f;
#pragma unroll
    for (int a = 0; a < AA_; a++) {
        float s = 0.0f;
#pragma unroll
        for (int i = 0; i < 8; i++) s += yv[i] * sw[a * 256 + lane + 32 * i];
#pragma unroll
        for (int o = 16; o; o >>= 1) s += __shfl_xor_sync(0xffffffffu, s, o);
        if (lane == a) logit = s;
    }

    float v = (lane < AA_) ? (logit + lpb[lane]) : -3.402823466e+38f;
    float mx = v;
#pragma unroll
    for (int o = 16; o; o >>= 1)
        mx = fmaxf(mx, __shfl_xor_sync(0xffffffffu, mx, o));
    float ev = (lane < AA_) ? __expf(v - mx) : 0.0f;
    float se = ev;
#pragma unroll
    for (int o = 16; o; o >>= 1) se += __shfl_xor_sync(0xffffffffu, se, o);
    float ls = __logf(se);

    if (lane < AA_) {
        int m = warp, t = m >> 5, b = m & 31;
        out[(size_t)b * T_ * AA_ + t * AA_ + lane] = v - mx - ls;
    }
}

// ---------------------------------------------------------------------------
// Launch
// ---------------------------------------------------------------------------
extern "C" void kernel_launch(void* const* d_in, const int* in_sizes, int n_in,
                              void* d_out, int out_size)
{
    const float* x   = (const float*)d_in[0];
    const float* w0  = (const float*)d_in[2];
    const float* wc0 = (const float*)d_in[3];
    const float* bb0 = (const float*)d_in[4];
    const float* w1  = (const float*)d_in[5];
    const float* wc1 = (const float*)d_in[6];
    const float* bb1 = (const float*)d_in[7];
    const float* fcw = (const float*)d_in[8];
    const float* fcb = (const float*)d_in[9];
    const float* lpw = (const float*)d_in[10];
    const float* lpb = (const float*)d_in[11];
    float* out = (float*)d_out;

    float *pU, *pY;
    __nv_bfloat16 *pA0h,*pA0l,*pA1h,*pA1l,*pA2h,*pA2l,*pB0h,*pB0l,*pB1h,*pB1l,*pFh,*pFl;
    cudaGetSymbolAddress((void**)&pU,   g_U);
    cudaGetSymbolAddress((void**)&pY,   g_y);
    cudaGetSymbolAddress((void**)&pA0h, g_A0h); cudaGetSymbolAddress((void**)&pA0l, g_A0l);
    cudaGetSymbolAddress((void**)&pA1h, g_A1h); cudaGetSymbolAddress((void**)&pA1l, g_A1l);
    cudaGetSymbolAddress((void**)&pA2h, g_A2h); cudaGetSymbolAddress((void**)&pA2l, g_A2l);
    cudaGetSymbolAddress((void**)&pB0h, g_B0h); cudaGetSymbolAddress((void**)&pB0l, g_B0l);
    cudaGetSymbolAddress((void**)&pB1h, g_B1h); cudaGetSymbolAddress((void**)&pB1l, g_B1l);
    cudaGetSymbolAddress((void**)&pFh,  g_FCh); cudaGetSymbolAddress((void**)&pFl,  g_FCl);

    cudaFuncSetAttribute(gemm_mma, cudaFuncAttributeMaxDynamicSharedMemorySize,
                         GEMM_SMEM);

    pack_weights<<<(PK_TOT + 255) / 256, 256>>>(w0, w1, fcw);
    convert_x<<<(32768 * 64) / 256, 256>>>(x);

    // Layer 0: U[n] = A0 (32768x256) * B0[n]^T (1024x256)
    dim3 gU(8, 256);
    for (int n = 0; n < 2; n++)
        gemm_mma<<<gU, 256, GEMM_SMEM>>>(pA0h, pA0l,
            pB0h + (size_t)n * 262144, pB0l + (size_t)n * 262144,
            pU + (size_t)n * M_ * 1024, nullptr, /*K=*/256, /*ldc=*/1024);

    sru_scan<<<256, 64>>>(pU, wc0, bb0, pA1h, pA1l);

    // Layer 1: K=512
    for (int n = 0; n < 2; n++)
        gemm_mma<<<gU, 256, GEMM_SMEM>>>(pA1h, pA1l,
            pB1h + (size_t)n * 524288, pB1l + (size_t)n * 524288,
            pU + (size_t)n * M_ * 1024, nullptr, /*K=*/512, /*ldc=*/1024);

    sru_scan<<<256, 64>>>(pU, wc1, bb1, pA2h, pA2l);

    // FC1: (32768x512) * (256x512)^T + bias
    dim3 gF(2, 256);
    gemm_mma<<<gF, 256, GEMM_SMEM>>>(pA2h, pA2l, pFh, pFl, pY, fcb,
                                     /*K=*/512, /*ldc=*/256);

    head_kernel<<<M_ / 8, 256>>>(pY, lpw, lpb, out);
}

// round 16
// speedup vs baseline: 2.3388x; 1.0013x over previous
#include <cuda_runtime.h>
#include <cuda_bf16.h>
#include <cstdint>

// Problem dims
#define T_   1024
#define B_   32
#define DIN_ 256
#define H_   256
#define AA_  21
#define M_   (T_*B_)   // 32768

// ---------------------------------------------------------------------------
// Device scratch (no cudaMalloc allowed)
// ---------------------------------------------------------------------------
__device__ float g_U [2u*32768u*1024u];          // GEMM U output per dir (fp32)
__device__ float g_y [32768u*256u];              // fc1 output (fp32)

// bf16 hi/lo operands, plain row-major [rows][K]
__device__ __nv_bfloat16 g_A0h[32768u*256u], g_A0l[32768u*256u];   // x rows m=t*B+b
__device__ __nv_bfloat16 g_A1h[32768u*512u], g_A1l[32768u*512u];   // scan0 out
__device__ __nv_bfloat16 g_A2h[32768u*512u], g_A2l[32768u*512u];   // scan1 out
__device__ __nv_bfloat16 g_B0h[2u*1024u*256u], g_B0l[2u*1024u*256u];
__device__ __nv_bfloat16 g_B1h[2u*1024u*512u], g_B1l[2u*1024u*512u];
__device__ __nv_bfloat16 g_FCh[256u*512u],     g_FCl[256u*512u];

// ---------------------------------------------------------------------------
// Helpers
// ---------------------------------------------------------------------------
__device__ __forceinline__ uint32_t smem_u32(const void* p) {
    uint32_t a;
    asm("{ .reg .u64 t; cvta.to.shared.u64 t, %1; cvt.u32.u64 %0, t; }"
        : "=r"(a) : "l"(p));
    return a;
}
__device__ __forceinline__ void cp16(uint32_t dst, const void* src) {
    asm volatile("cp.async.cg.shared.global [%0], [%1], 16;"
                 :: "r"(dst), "l"(src));
}
__device__ __forceinline__ void ldsm4(uint32_t* r, uint32_t a) {
    asm volatile("ldmatrix.sync.aligned.m8n8.x4.shared.b16 {%0,%1,%2,%3}, [%4];"
                 : "=r"(r[0]), "=r"(r[1]), "=r"(r[2]), "=r"(r[3]) : "r"(a));
}
__device__ __forceinline__ void mma16816(float* c, const uint32_t* a,
                                         const uint32_t* b) {
    asm volatile("mma.sync.aligned.m16n8k16.row.col.f32.bf16.bf16.f32 "
                 "{%0,%1,%2,%3}, {%4,%5,%6,%7}, {%8,%9}, {%0,%1,%2,%3};"
                 : "+f"(c[0]), "+f"(c[1]), "+f"(c[2]), "+f"(c[3])
                 : "r"(a[0]), "r"(a[1]), "r"(a[2]), "r"(a[3]),
                   "r"(b[0]), "r"(b[1]));
}
__device__ __forceinline__ void split_store(__nv_bfloat16* hi, __nv_bfloat16* lo,
                                            size_t off, float v) {
    __nv_bfloat16 h = __float2bfloat16(v);
    hi[off] = h;
    lo[off] = __float2bfloat16(v - __bfloat162float(h));
}

// ---------------------------------------------------------------------------
// Weight pack: fp32 weights -> bf16 hi/lo row-major B matrices [n_out][k]
// ---------------------------------------------------------------------------
#define PK_S0 (2*1024*256)
#define PK_S1 (2*1024*512)
#define PK_S2 (256*512)
#define PK_TOT (PK_S0 + PK_S1 + PK_S2)

__global__ void pack_weights(const float* __restrict__ w0,
                             const float* __restrict__ w1,
                             const float* __restrict__ fcw)
{
    int i = blockIdx.x * blockDim.x + threadIdx.x;
    if (i < PK_S0) {
        int n = i / 262144, r = i % 262144;
        int c = r >> 8, d = r & 255;               // row c = h*4+k, col d
        int k = c & 3, h = c >> 2;
        float v = w0[((d*2 + n)*4 + k)*H_ + h];
        split_store(g_B0h, g_B0l, (size_t)i, v);   // off = n*262144 + c*256 + d
        return;
    }
    int j = i - PK_S0;
    if (j < PK_S1) {
        int n = j / 524288, r = j % 524288;
        int c = r >> 9, d = r & 511;
        int k = c & 3, h = c >> 2;
        float v = w1[((d*2 + n)*4 + k)*H_ + h];
        split_store(g_B1h, g_B1l, (size_t)j, v);
        return;
    }
    int l = j - PK_S1;
    if (l < PK_S2) {                               // fc1_w is (H,2H) row-major already
        split_store(g_FCh, g_FCl, (size_t)l, fcw[l]);
    }
}

// ---------------------------------------------------------------------------
// x (B,T,DIN) fp32 -> row-major bf16 hi/lo A0 with row m = t*B + b
// ---------------------------------------------------------------------------
__global__ void convert_x(const float* __restrict__ x)
{
    int id = blockIdx.x * blockDim.x + threadIdx.x;   // < 32768*64
    int m = id >> 6, q = id & 63;
    int b = m & 31, t = m >> 5;
    float4 v = ((const float4*)x)[(size_t)(b * T_ + t) * 64 + q];
    size_t off = (size_t)m * 256 + (q << 2);
    __nv_bfloat16 h0 = __float2bfloat16(v.x), h1 = __float2bfloat16(v.y);
    __nv_bfloat16 h2 = __float2bfloat16(v.z), h3 = __float2bfloat16(v.w);
    ushort4 hs = make_ushort4(__bfloat16_as_ushort(h0), __bfloat16_as_ushort(h1),
                              __bfloat16_as_ushort(h2), __bfloat16_as_ushort(h3));
    ushort4 ls = make_ushort4(
        __bfloat16_as_ushort(__float2bfloat16(v.x - __bfloat162float(h0))),
        __bfloat16_as_ushort(__float2bfloat16(v.y - __bfloat162float(h1))),
        __bfloat16_as_ushort(__float2bfloat16(v.z - __bfloat162float(h2))),
        __bfloat16_as_ushort(__float2bfloat16(v.w - __bfloat162float(h3))));
    *(ushort4*)(g_A0h + off) = hs;
    *(ushort4*)(g_A0l + off) = ls;
}

// ---------------------------------------------------------------------------
// bf16x3-split GEMM on mma.sync (HMMA): C[m][c] = sum_k A[m][k]*B[c][k]
// Block 128x128xBK32, 256 thr, 8 warps (warp tile 32x64), cp.async 3-stage.
// SMEM tile rows padded to 40 bf16 (80B) -> conflict-free ldmatrix.
// ---------------------------------------------------------------------------
#define TILE_B   10240          // 128 rows * 80 bytes
#define STAGE_B  (4*TILE_B)     // Ah, Al, Bh, Bl
#define NSTAGE   3
#define GEMM_SMEM (NSTAGE*STAGE_B)

__device__ __forceinline__ void load_stage(uint32_t st,
    const __nv_bfloat16* gAh, const __nv_bfloat16* gAl,
    const __nv_bfloat16* gBh, const __nv_bfloat16* gBl,
    int K, int kt, int tid)
{
    const __nv_bfloat16* base[4] = {gAh, gAl, gBh, gBl};
#pragma unroll
    for (int tl = 0; tl < 4; tl++) {
        uint32_t doff = st + tl * TILE_B;
#pragma unroll
        for (int i = 0; i < 2; i++) {
            int q = tid + i * 256;           // 512 16B chunks per tile
            int row = q >> 2, c16 = q & 3;
            cp16(doff + row * 80 + c16 * 16,
                 base[tl] + (size_t)row * K + kt * 32 + c16 * 8);
        }
    }
}

__global__ void __launch_bounds__(256, 1)
gemm_mma(const __nv_bfloat16* __restrict__ Ah, const __nv_bfloat16* __restrict__ Al,
         const __nv_bfloat16* __restrict__ Bh, const __nv_bfloat16* __restrict__ Bl,
         float* __restrict__ C, const float* __restrict__ bias, int K, int ldc)
{
    extern __shared__ char smem[];
    const uint32_t sb = smem_u32(smem);
    const int tid = threadIdx.x;
    const int lane = tid & 31, wid = tid >> 5;
    const int wm = wid & 3, wn = wid >> 2;    // 4 x 2 warp grid

    const __nv_bfloat16* gAh = Ah + (size_t)blockIdx.y * 128 * K;
    const __nv_bfloat16* gAl = Al + (size_t)blockIdx.y * 128 * K;
    const __nv_bfloat16* gBh = Bh + (size_t)blockIdx.x * 128 * K;
    const __nv_bfloat16* gBl = Bl + (size_t)blockIdx.x * 128 * K;

    // ldmatrix per-thread byte offsets within a tile
    uint32_t aoff[2], boff[4];
#pragma unroll
    for (int mt = 0; mt < 2; mt++) {
        int row = wm * 32 + mt * 16 + (lane & 15);
        aoff[mt] = row * 80 + ((lane >> 4) & 1) * 16;
    }
#pragma unroll
    for (int p = 0; p < 4; p++) {
        int row = wn * 64 + p * 16 + ((lane >> 4) & 1) * 8 + (lane & 7);
        boff[p] = row * 80 + ((lane >> 3) & 1) * 16;
    }

    float acc[2][8][4];
#pragma unroll
    for (int a = 0; a < 2; a++)
#pragma unroll
        for (int b = 0; b < 8; b++)
#pragma unroll
            for (int c = 0; c < 4; c++) acc[a][b][c] = 0.0f;

    const int KT = K >> 5;
    load_stage(sb, gAh, gAl, gBh, gBl, K, 0, tid);
    asm volatile("cp.async.commit_group;");
    load_stage(sb + STAGE_B, gAh, gAl, gBh, gBl, K, 1, tid);
    asm volatile("cp.async.commit_group;");

    for (int kt = 0; kt < KT; kt++) {
        asm volatile("cp.async.wait_group 1;");
        __syncthreads();
        uint32_t st = sb + (kt % NSTAGE) * STAGE_B;
        uint32_t s_ah = st, s_al = st + TILE_B;
        uint32_t s_bh = st + 2*TILE_B, s_bl = st + 3*TILE_B;
#pragma unroll
        for (int kk = 0; kk < 2; kk++) {
            uint32_t ah[2][4], al[2][4];
#pragma unroll
            for (int mt = 0; mt < 2; mt++) {
                ldsm4(ah[mt], s_ah + aoff[mt] + kk * 32);
                ldsm4(al[mt], s_al + aoff[mt] + kk * 32);
            }
#pragma unroll
            for (int p = 0; p < 4; p++) {
                uint32_t bh[4], bl[4];
                ldsm4(bh, s_bh + boff[p] + kk * 32);
                ldsm4(bl, s_bl + boff[p] + kk * 32);
#pragma unroll
                for (int mt = 0; mt < 2; mt++) {
                    mma16816(acc[mt][2*p],   ah[mt], bh);
                    mma16816(acc[mt][2*p],   ah[mt], bl);
                    mma16816(acc[mt][2*p],   al[mt], bh);
                    mma16816(acc[mt][2*p+1], ah[mt], bh + 2);
                    mma16816(acc[mt][2*p+1], ah[mt], bl + 2);
                    mma16816(acc[mt][2*p+1], al[mt], bh + 2);
                }
            }
        }
        __syncthreads();
        if (kt + 2 < KT)
            load_stage(sb + ((kt + 2) % NSTAGE) * STAGE_B,
                       gAh, gAl, gBh, gBl, K, kt + 2, tid);
        asm volatile("cp.async.commit_group;");
    }

    // epilogue: c0,c1 -> (m, n..n+1); c2,c3 -> (m+8, n..n+1)
    const int mbase = blockIdx.y * 128 + wm * 32;
    const int nbase = blockIdx.x * 128 + wn * 64;
#pragma unroll
    for (int mt = 0; mt < 2; mt++) {
        int m = mbase + mt * 16 + (lane >> 2);
#pragma unroll
        for (int nj = 0; nj < 8; nj++) {
            int n = nbase + nj * 8 + (lane & 3) * 2;
            float b0 = 0.0f, b1 = 0.0f;
            if (bias) { b0 = bias[n]; b1 = bias[n + 1]; }
            float2 v0 = make_float2(acc[mt][nj][0] + b0, acc[mt][nj][1] + b1);
            float2 v1 = make_float2(acc[mt][nj][2] + b0, acc[mt][nj][3] + b1);
            *(float2*)(C + (size_t)m * ldc + n)       = v0;
            *(float2*)(C + (size_t)(m + 8) * ldc + n) = v1;
        }
    }
}

// ---------------------------------------------------------------------------
// SRU recurrence: one thread per (dir,b,h), 1024 sequential steps, 8-deep
// prefetch. 256 blocks x 64 threads -> covers all SMs. Writes next layer's
// A operand directly as bf16 hi/lo, row-major [m][512], col = dir*256+h.
// ---------------------------------------------------------------------------
__device__ __forceinline__ float sigm_(float x) {
    return __fdividef(1.0f, 1.0f + __expf(-x));
}

__global__ void __launch_bounds__(64)
sru_scan(const float* __restrict__ U, const float* __restrict__ wc,
         const float* __restrict__ bb,
         __nv_bfloat16* __restrict__ Ohi, __nv_bfloat16* __restrict__ Olo)
{
    int g   = blockIdx.x * 64 + threadIdx.x;   // 0..16383
    int dir = g >> 13;
    int e   = g & 8191;
    int h   = e & 255;
    int b   = e >> 8;

    const float vf = wc[(dir*2 + 0)*H_ + h];
    const float vr = wc[(dir*2 + 1)*H_ + h];
    const float bf = bb[(dir*2 + 0)*H_ + h];
    const float br = bb[(dir*2 + 1)*H_ + h];

    const float4* Ud = (const float4*)(U + (size_t)dir * M_ * 1024u);
    const int colg = dir * 256 + h;

    float c = 0.0f;
    float4 pf[8];
#pragma unroll
    for (int i = 0; i < 8; i++) {
        int tp = dir ? (T_ - 1 - i) : i;
        pf[i] = Ud[(size_t)(tp * B_ + b) * 256 + h];
    }

    for (int t = 0; t < T_; t += 8) {
#pragma unroll
        for (int j = 0; j < 8; j++) {
            float4 u = pf[j];
            int tn = t + 8 + j;
            if (tn < T_) {
                int tp = dir ? (T_ - 1 - tn) : tn;
                pf[j] = Ud[(size_t)(tp * B_ + b) * 256 + h];
            }
            float f = sigm_(u.y + __fmaf_rn(vf, c, bf));
            float r = sigm_(u.z + __fmaf_rn(vr, c, br));
            c = __fmaf_rn(f, c - u.x, u.x);
            float hv = __fmaf_rn(r, c - u.w, u.w);

            int tcur = t + j;
            int tp = dir ? (T_ - 1 - tcur) : tcur;
            size_t off = (size_t)(tp * B_ + b) * 512 + colg;
            split_store(Ohi, Olo, off, hv);
        }
    }
}

// ---------------------------------------------------------------------------
// Head: logits = y @ lp_w^T + lp_b (K=256, N=21), then log_softmax over 21.
// One warp per row m. Output (B,T,AA): m = t*B + b.
// ---------------------------------------------------------------------------
__global__ void __launch_bounds__(256)
head_kernel(const float* __restrict__ Y, const float* __restrict__ lpw,
            const float* __restrict__ lpb, float* __restrict__ out)
{
    __shared__ float sw[AA_ * 256];
    for (int i = threadIdx.x; i < AA_ * 256; i += blockDim.x) sw[i] = lpw[i];
    __syncthreads();

    int warp = (blockIdx.x * blockDim.x + threadIdx.x) >> 5;
    int lane = threadIdx.x & 31;
    if (warp >= M_) return;

    const float* y = Y + (size_t)warp * 256;
    float yv[8];
#pragma unroll
    for (int i = 0; i < 8; i++) yv[i] = y[lane + 32 * i];

    float logit = 0.0f;
#pragma unroll
    for (int a = 0; a < AA_; a++) {
        float s = 0.0f;
#pragma unroll
        for (int i = 0; i < 8; i++) s += yv[i] * sw[a * 256 + lane + 32 * i];
#pragma unroll
        for (int o = 16; o; o >>= 1) s += __shfl_xor_sync(0xffffffffu, s, o);
        if (lane == a) logit = s;
    }

    float v = (lane < AA_) ? (logit + lpb[lane]) : -3.402823466e+38f;
    float mx = v;
#pragma unroll
    for (int o = 16; o; o >>= 1)
        mx = fmaxf(mx, __shfl_xor_sync(0xffffffffu, mx, o));
    float ev = (lane < AA_) ? __expf(v - mx) : 0.0f;
    float se = ev;
#pragma unroll
    for (int o = 16; o; o >>= 1) se += __shfl_xor_sync(0xffffffffu, se, o);
    float ls = __logf(se);

    if (lane < AA_) {
        int m = warp, t = m >> 5, b = m & 31;
        out[(size_t)b * T_ * AA_ + t * AA_ + lane] = v - mx - ls;
    }
}

// ---------------------------------------------------------------------------
// Launch
// ---------------------------------------------------------------------------
extern "C" void kernel_launch(void* const* d_in, const int* in_sizes, int n_in,
                              void* d_out, int out_size)
{
    const float* x   = (const float*)d_in[0];
    const float* w0  = (const float*)d_in[2];
    const float* wc0 = (const float*)d_in[3];
    const float* bb0 = (const float*)d_in[4];
    const float* w1  = (const float*)d_in[5];
    const float* wc1 = (const float*)d_in[6];
    const float* bb1 = (const float*)d_in[7];
    const float* fcw = (const float*)d_in[8];
    const float* fcb = (const float*)d_in[9];
    const float* lpw = (const float*)d_in[10];
    const float* lpb = (const float*)d_in[11];
    float* out = (float*)d_out;

    float *pU, *pY;
    __nv_bfloat16 *pA0h,*pA0l,*pA1h,*pA1l,*pA2h,*pA2l,*pB0h,*pB0l,*pB1h,*pB1l,*pFh,*pFl;
    cudaGetSymbolAddress((void**)&pU,   g_U);
    cudaGetSymbolAddress((void**)&pY,   g_y);
    cudaGetSymbolAddress((void**)&pA0h, g_A0h); cudaGetSymbolAddress((void**)&pA0l, g_A0l);
    cudaGetSymbolAddress((void**)&pA1h, g_A1h); cudaGetSymbolAddress((void**)&pA1l, g_A1l);
    cudaGetSymbolAddress((void**)&pA2h, g_A2h); cudaGetSymbolAddress((void**)&pA2l, g_A2l);
    cudaGetSymbolAddress((void**)&pB0h, g_B0h); cudaGetSymbolAddress((void**)&pB0l, g_B0l);
    cudaGetSymbolAddress((void**)&pB1h, g_B1h); cudaGetSymbolAddress((void**)&pB1l, g_B1l);
    cudaGetSymbolAddress((void**)&pFh,  g_FCh); cudaGetSymbolAddress((void**)&pFl,  g_FCl);

    cudaFuncSetAttribute(gemm_mma, cudaFuncAttributeMaxDynamicSharedMemorySize,
                         GEMM_SMEM);

    pack_weights<<<(PK_TOT + 255) / 256, 256>>>(w0, w1, fcw);
    convert_x<<<(32768 * 64) / 256, 256>>>(x);

    // Layer 0: U[n] = A0 (32768x256) * B0[n]^T (1024x256)
    dim3 gU(8, 256);
    for (int n = 0; n < 2; n++)
        gemm_mma<<<gU, 256, GEMM_SMEM>>>(pA0h, pA0l,
            pB0h + (size_t)n * 262144, pB0l + (size_t)n * 262144,
            pU + (size_t)n * M_ * 1024, nullptr, /*K=*/256, /*ldc=*/1024);

    sru_scan<<<256, 64>>>(pU, wc0, bb0, pA1h, pA1l);

    // Layer 1: K=512
    for (int n = 0; n < 2; n++)
        gemm_mma<<<gU, 256, GEMM_SMEM>>>(pA1h, pA1l,
            pB1h + (size_t)n * 524288, pB1l + (size_t)n * 524288,
            pU + (size_t)n * M_ * 1024, nullptr, /*K=*/512, /*ldc=*/1024);

    sru_scan<<<256, 64>>>(pU, wc1, bb1, pA2h, pA2l);

    // FC1: (32768x512) * (256x512)^T + bias
    dim3 gF(2, 256);
    gemm_mma<<<gF, 256, GEMM_SMEM>>>(pA2h, pA2l, pFh, pFl, pY, fcb,
                                     /*K=*/512, /*ldc=*/256);

    head_kernel<<<M_ / 8, 256>>>(pY, lpw, lpb, out);
}